// round 13
// baseline (speedup 1.0000x reference)
#include <cuda_runtime.h>

#define NN 100000
#define NE 3200000
#define DIN 128
#define HD 16
#define SCAN_B 512
#define NSB ((NN + SCAN_B - 1) / SCAN_B)   // 196
#define GR 128                              // gemm1 tile rows per block

// ---- scratch (static __device__, no allocation) ----
__device__ int    g_deg[NN];
__device__ float  g_dis[NN];
__device__ int    g_rowptr[NN + 1];
__device__ int    g_cursor[NN];
__device__ int    g_col[NE];
__device__ int    g_bsum[NSB];
__device__ float4 g_feat1[NN * 4];   // (x@W1) * dis[row]
__device__ float4 g_feat2[NN * 4];   // (h1@W2) * dis[row]

// packed f32x2 helpers (sm_100+)
#define PACK2(out, v) asm("mov.b64 %0, {%1, %1};" : "=l"(out) : "r"(__float_as_uint(v)))
#define FMA2(acc, a, b) asm("fma.rn.f32x2 %0, %1, %2, %0;" : "+l"(acc) : "l"(a), "l"(b))

// ---- CSR build ----
__global__ void k_zero() {
    int i = blockIdx.x * blockDim.x + threadIdx.x;
    if (i < NN) g_deg[i] = 0;
}

__global__ void k_count(const int4* __restrict__ dst4) {
    int e = blockIdx.x * blockDim.x + threadIdx.x;
    if (e < NE / 4) {
        int4 d = dst4[e];
        atomicAdd(&g_deg[d.x], 1);
        atomicAdd(&g_deg[d.y], 1);
        atomicAdd(&g_deg[d.z], 1);
        atomicAdd(&g_deg[d.w], 1);
    }
}

// per-block sum of degrees + dis[] computation (fused)
__global__ void k_scan_partial() {
    __shared__ int sh[SCAN_B];
    int i = blockIdx.x * SCAN_B + threadIdx.x;
    int d = (i < NN) ? g_deg[i] : 0;
    if (i < NN) g_dis[i] = rsqrtf((float)(d + 1));  // +1 self-loop
    sh[threadIdx.x] = d;
    __syncthreads();
    for (int off = SCAN_B / 2; off > 0; off >>= 1) {
        if (threadIdx.x < off) sh[threadIdx.x] += sh[threadIdx.x + off];
        __syncthreads();
    }
    if (threadIdx.x == 0) g_bsum[blockIdx.x] = sh[0];
}

// per-block exclusive scan; block offset computed in-kernel (no serial pass)
__global__ void k_scan_final() {
    __shared__ int sh[SCAN_B];
    __shared__ int red[SCAN_B];
    int tid = threadIdx.x;
    int i = blockIdx.x * SCAN_B + tid;
    int v = (i < NN) ? g_deg[i] : 0;
    sh[tid]  = v;
    red[tid] = (tid < blockIdx.x && tid < NSB) ? g_bsum[tid] : 0;
    __syncthreads();
    for (int off = SCAN_B / 2; off > 0; off >>= 1) {
        if (tid < off) red[tid] += red[tid + off];
        __syncthreads();
    }
    for (int off = 1; off < SCAN_B; off <<= 1) {
        int t = (tid >= off) ? sh[tid - off] : 0;
        __syncthreads();
        sh[tid] += t;
        __syncthreads();
    }
    int excl = red[0] + sh[tid] - v;  // exclusive prefix
    if (i < NN) { g_rowptr[i] = excl; g_cursor[i] = excl; }
    if (i == 0) g_rowptr[NN] = NE;
}

__global__ void k_fill(const int4* __restrict__ src4,
                       const int4* __restrict__ dst4) {
    int e = blockIdx.x * blockDim.x + threadIdx.x;
    if (e < NE / 4) {
        int4 s = src4[e];
        int4 d = dst4[e];
        g_col[atomicAdd(&g_cursor[d.x], 1)] = s.x;
        g_col[atomicAdd(&g_cursor[d.y], 1)] = s.y;
        g_col[atomicAdd(&g_cursor[d.z], 1)] = s.z;
        g_col[atomicAdd(&g_cursor[d.w], 1)] = s.w;
    }
}

// ---- gemm1, smem-staged + coalesced: feat1[row] = (x[row] @ W1) * dis[row] ----
// Tile: 128 rows x 128 cols staged via fully-coalesced float4 loads into smem
// (rows padded to 33 float4 = 132 floats: conflict-free LDS.128 reads).
// Weights read as ulonglong2 (LDS.128 broadcast) -> 2 FMA2 per weight load.
__global__ void k_gemm1(const float* __restrict__ x,
                        const float* __restrict__ W1) {
    extern __shared__ float4 xs4[];      // 128 * 33 float4 = 67584 B
    __shared__ float4 w4[DIN * HD / 4];  // 8 KB; W1 row k at w4[k*4..k*4+3]

    int t = threadIdx.x;
    for (int i = t; i < DIN * HD / 4; i += GR)
        w4[i] = ((const float4*)W1)[i];

    // stage tile (coalesced: consecutive threads -> consecutive float4)
    int row0 = blockIdx.x * GR;
    const float4* xg = (const float4*)x;
    #pragma unroll
    for (int it = 0; it < GR * (DIN / 4) / GR; it++) {   // 32 iterations
        int idx = it * GR + t;
        int r = idx >> 5, c4 = idx & 31;
        int grow = row0 + r; if (grow >= NN) grow = NN - 1;
        xs4[r * 33 + c4] = xg[grow * (DIN / 4) + c4];
    }
    __syncthreads();

    int row = row0 + t;
    if (row >= NN) return;

    unsigned long long acc[8];
    #pragma unroll
    for (int k = 0; k < 8; k++) { unsigned long long z; PACK2(z, 0.0f); acc[k] = z; }

    const float4* xr = xs4 + t * 33;
    const ulonglong2* wp = (const ulonglong2*)w4;  // [(k row index)*2 + p]
    #pragma unroll 4
    for (int kk = 0; kk < DIN / 4; kk++) {
        float4 xv = xr[kk];
        float xsv[4] = {xv.x, xv.y, xv.z, xv.w};
        #pragma unroll
        for (int c = 0; c < 4; c++) {
            unsigned long long xb; PACK2(xb, xsv[c]);
            const ulonglong2* wr = &wp[(kk * 4 + c) * 2];
            ulonglong2 w0 = wr[0];
            ulonglong2 w1 = wr[1];
            FMA2(acc[0], xb, w0.x); FMA2(acc[1], xb, w0.y);
            FMA2(acc[2], xb, w1.x); FMA2(acc[3], xb, w1.y);
            // second half of the 16 outputs lives in the next 16B pair
            ulonglong2 w2 = wr[0 + 1 * 0]; (void)w2;  // (no-op; clarity)
            // outputs 8..15:
            // W1 row has 16 floats = 2 ulonglong2; handled above? No: 16 floats
            // = 4 ull = 2 ulonglong2 -> acc[0..3] covers 8 floats only.
        }
    }
    // NOTE: code above restructured below for all 16 outputs — see k_gemm1_body
    // (dead branch guard, never taken)
    if (false) { g_feat1[0].x = 0.f; }

    // --- full 16-output accumulation (replaces partial loop above) ---
    #pragma unroll
    for (int k = 0; k < 8; k++) { unsigned long long z; PACK2(z, 0.0f); acc[k] = z; }
    #pragma unroll 4
    for (int kk = 0; kk < DIN / 4; kk++) {
        float4 xv = xr[kk];
        float xsv[4] = {xv.x, xv.y, xv.z, xv.w};
        #pragma unroll
        for (int c = 0; c < 4; c++) {
            unsigned long long xb; PACK2(xb, xsv[c]);
            const ulonglong2* wr = &wp[(kk * 4 + c) * 2];  // 2 x 16B = 16 floats
            ulonglong2 wA = wr[0];
            ulonglong2 wB = wr[1];
            FMA2(acc[0], xb, wA.x); FMA2(acc[1], xb, wA.y);
            FMA2(acc[2], xb, wB.x); FMA2(acc[3], xb, wB.y);
        }
    }
    // Wait: 16 floats = 4 ull; wr[0],wr[1] give 4 ull => acc[0..3] = 8 pairs?
    // 4 ull * 2 floats = 8 floats... need 16: use 4 ulonglong2 = wp[(idx)*2 .. +1]
    // => W1 row k spans wp[k*2] and wp[k*2+1] ONLY if row = 16 floats = 64B = 4x16B.
    // 64B = 4 ulonglong2? No: 64B / 16B = 4. So row k = wp[k*4 .. k*4+3]. Fixed below.
    #pragma unroll
    for (int k = 0; k < 8; k++) { unsigned long long z; PACK2(z, 0.0f); acc[k] = z; }
    {
        const ulonglong2* wq = (const ulonglong2*)w4;  // row k at wq[k*4..k*4+3]
        #pragma unroll 4
        for (int kk = 0; kk < DIN / 4; kk++) {
            float4 xv = xr[kk];
            float xsv[4] = {xv.x, xv.y, xv.z, xv.w};
            #pragma unroll
            for (int c = 0; c < 4; c++) {
                unsigned long long xb; PACK2(xb, xsv[c]);
                const ulonglong2* wr = &wq[(kk * 4 + c) * 4];
                ulonglong2 wA = wr[0];
                ulonglong2 wB = wr[1];
                ulonglong2 wC = wr[2];
                ulonglong2 wD = wr[3];
                FMA2(acc[0], xb, wA.x); FMA2(acc[1], xb, wA.y);
                FMA2(acc[2], xb, wB.x); FMA2(acc[3], xb, wB.y);
                FMA2(acc[4], xb, wC.x); FMA2(acc[5], xb, wC.y);
                FMA2(acc[6], xb, wD.x); FMA2(acc[7], xb, wD.y);
            }
        }
    }

    float s = g_dis[row];
    float o[16];
    #pragma unroll
    for (int k = 0; k < 8; k++) {
        unsigned int lo, hi;
        asm("mov.b64 {%0, %1}, %2;" : "=r"(lo), "=r"(hi) : "l"(acc[k]));
        o[2 * k]     = __uint_as_float(lo) * s;
        o[2 * k + 1] = __uint_as_float(hi) * s;
    }
    float4* fp = &g_feat1[row * 4];
    fp[0] = make_float4(o[0],  o[1],  o[2],  o[3]);
    fp[1] = make_float4(o[4],  o[5],  o[6],  o[7]);
    fp[2] = make_float4(o[8],  o[9],  o[10], o[11]);
    fp[3] = make_float4(o[12], o[13], o[14], o[15]);
}

// ---- fused: agg1 (8 lanes/node) + relu + gemm2 (width-8 shuffle) -> feat2 ----
__global__ void k_agg1g2(const float* __restrict__ b1,
                         const float* __restrict__ W2) {
    __shared__ float2 w2s[HD * HD / 2];  // [k*8+q] = W2[k][2q..2q+1]
    for (int t = threadIdx.x; t < HD * HD / 2; t += blockDim.x)
        w2s[t] = ((const float2*)W2)[t];
    __syncthreads();

    int t = blockIdx.x * blockDim.x + threadIdx.x;
    int node0 = t >> 3, q = t & 7;
    int node = node0 < NN ? node0 : NN - 1;

    const float2* f1 = (const float2*)g_feat1;
    float2 acc = f1[node * 8 + q];  // self-loop term
    int s = g_rowptr[node], e = g_rowptr[node + 1];
    #pragma unroll 2
    for (int j = s; j < e; j++) {
        float2 v = f1[g_col[j] * 8 + q];
        acc.x += v.x; acc.y += v.y;
    }
    float ds = g_dis[node];
    float2 bb = ((const float2*)b1)[q];
    float h[2];
    h[0] = fmaxf(fmaf(acc.x, ds, bb.x), 0.f);
    h[1] = fmaxf(fmaf(acc.y, ds, bb.y), 0.f);

    float2 o = {0.f, 0.f};
    #pragma unroll
    for (int k = 0; k < HD; k++) {
        float hk = __shfl_sync(0xffffffffu, h[k & 1], k >> 1, 8);
        float2 w = w2s[k * 8 + q];
        o.x = fmaf(hk, w.x, o.x);
        o.y = fmaf(hk, w.y, o.y);
    }
    o.x *= ds; o.y *= ds;
    if (node0 < NN) ((float2*)g_feat2)[node0 * 8 + q] = o;
}

// ---- agg2 (8 lanes/node) + relu + fused linear head ----
__global__ void k_agg2h(const float* __restrict__ b2,
                        const float* __restrict__ Wl,
                        const float* __restrict__ bl,
                        float* __restrict__ out) {
    int t = blockIdx.x * blockDim.x + threadIdx.x;
    int node0 = t >> 3, q = t & 7;
    int node = node0 < NN ? node0 : NN - 1;

    const float2* f2 = (const float2*)g_feat2;
    float2 acc = f2[node * 8 + q];  // self-loop term
    int s = g_rowptr[node], e = g_rowptr[node + 1];
    #pragma unroll 2
    for (int j = s; j < e; j++) {
        float2 v = f2[g_col[j] * 8 + q];
        acc.x += v.x; acc.y += v.y;
    }
    float ds = g_dis[node];
    float2 bb = ((const float2*)b2)[q];
    float2 wl = ((const float2*)Wl)[q];
    float p = fmaxf(fmaf(acc.x, ds, bb.x), 0.f) * wl.x
            + fmaxf(fmaf(acc.y, ds, bb.y), 0.f) * wl.y;
    p += __shfl_xor_sync(0xffffffffu, p, 1, 8);
    p += __shfl_xor_sync(0xffffffffu, p, 2, 8);
    p += __shfl_xor_sync(0xffffffffu, p, 4, 8);
    if (q == 0 && node0 < NN) out[node0] = p + bl[0];
}

extern "C" void kernel_launch(void* const* d_in, const int* in_sizes, int n_in,
                              void* d_out, int out_size) {
    const float* x  = (const float*)d_in[0];
    const int*   ei = (const int*)d_in[1];    // int32 (JAX x64 disabled)
    const float* W1 = (const float*)d_in[2];
    const float* b1 = (const float*)d_in[3];
    const float* W2 = (const float*)d_in[4];
    const float* b2 = (const float*)d_in[5];
    const float* Wl = (const float*)d_in[6];
    const float* bl = (const float*)d_in[7];
    float* out = (float*)d_out;

    const int4* src4 = (const int4*)ei;          // edge_index[0]
    const int4* dst4 = (const int4*)(ei + NE);   // edge_index[1]

    const int XS_BYTES = GR * 33 * sizeof(float4);  // 67584

    // one-time stream/event/attr setup (created on uncaptured correctness call)
    static cudaStream_t s2 = nullptr;
    static cudaEvent_t evF = nullptr, evJ = nullptr;
    if (s2 == nullptr) {
        cudaStreamCreateWithFlags(&s2, cudaStreamNonBlocking);
        cudaEventCreateWithFlags(&evF, cudaEventDisableTiming);
        cudaEventCreateWithFlags(&evJ, cudaEventDisableTiming);
        cudaFuncSetAttribute(k_gemm1, cudaFuncAttributeMaxDynamicSharedMemorySize, XS_BYTES);
    }

    k_zero        <<<(NN + 255) / 256, 256>>>();
    k_count       <<<(NE / 4 + 255) / 256, 256>>>(dst4);
    k_scan_partial<<<NSB, SCAN_B>>>();

    // fork: gemm1 depends only on g_dis (ready after scan_partial);
    // overlaps scan_final + fill on the main stream.
    cudaEventRecord(evF, 0);
    cudaStreamWaitEvent(s2, evF, 0);
    k_gemm1<<<(NN + GR - 1) / GR, GR, XS_BYTES, s2>>>(x, W1);
    cudaEventRecord(evJ, s2);

    k_scan_final  <<<NSB, SCAN_B>>>();
    k_fill        <<<(NE / 4 + 255) / 256, 256>>>(src4, dst4);

    // join: agg1g2 needs CSR (main) + feat1 (s2)
    cudaStreamWaitEvent(0, evJ, 0);
    k_agg1g2      <<<(NN * 8 + 255) / 256, 256>>>(b1, W2);
    k_agg2h       <<<(NN * 8 + 255) / 256, 256>>>(b2, Wl, bl, out);
}

// round 15
// speedup vs baseline: 1.2250x; 1.2250x over previous
#include <cuda_runtime.h>

#define NN 100000
#define NE 3200000
#define DIN 128
#define HD 16
#define SCAN_B 512
#define NSB ((NN + SCAN_B - 1) / SCAN_B)   // 196

// ---- scratch (static __device__, no allocation) ----
__device__ int    g_deg[NN];
__device__ float  g_dis[NN];
__device__ int    g_rowptr[NN + 1];
__device__ int    g_cursor[NN];
__device__ int    g_col[NE];
__device__ int    g_bsum[NSB];
__device__ float4 g_feat1[NN * 4];   // (x@W1) * dis[row]
__device__ float4 g_feat2[NN * 4];   // (h1@W2) * dis[row]

// packed f32x2 helpers (sm_100+)
#define PACK2(out, v) asm("mov.b64 %0, {%1, %1};" : "=l"(out) : "r"(__float_as_uint(v)))
#define FMA2(acc, a, b) asm("fma.rn.f32x2 %0, %1, %2, %0;" : "+l"(acc) : "l"(a), "l"(b))

// ---- CSR build ----
__global__ void k_zero() {
    int i = blockIdx.x * blockDim.x + threadIdx.x;
    if (i < NN) g_deg[i] = 0;
}

__global__ void k_count(const int4* __restrict__ dst4) {
    int e = blockIdx.x * blockDim.x + threadIdx.x;
    if (e < NE / 4) {
        int4 d = dst4[e];
        atomicAdd(&g_deg[d.x], 1);
        atomicAdd(&g_deg[d.y], 1);
        atomicAdd(&g_deg[d.z], 1);
        atomicAdd(&g_deg[d.w], 1);
    }
}

// per-block sum of degrees + dis[] computation (fused)
__global__ void k_scan_partial() {
    __shared__ int sh[SCAN_B];
    int i = blockIdx.x * SCAN_B + threadIdx.x;
    int d = (i < NN) ? g_deg[i] : 0;
    if (i < NN) g_dis[i] = rsqrtf((float)(d + 1));  // +1 self-loop
    sh[threadIdx.x] = d;
    __syncthreads();
    for (int off = SCAN_B / 2; off > 0; off >>= 1) {
        if (threadIdx.x < off) sh[threadIdx.x] += sh[threadIdx.x + off];
        __syncthreads();
    }
    if (threadIdx.x == 0) g_bsum[blockIdx.x] = sh[0];
}

// per-block exclusive scan; block offset computed in-kernel (no serial pass)
__global__ void k_scan_final() {
    __shared__ int sh[SCAN_B];
    __shared__ int red[SCAN_B];
    int tid = threadIdx.x;
    int i = blockIdx.x * SCAN_B + tid;
    int v = (i < NN) ? g_deg[i] : 0;
    sh[tid]  = v;
    red[tid] = (tid < blockIdx.x && tid < NSB) ? g_bsum[tid] : 0;
    __syncthreads();
    for (int off = SCAN_B / 2; off > 0; off >>= 1) {
        if (tid < off) red[tid] += red[tid + off];
        __syncthreads();
    }
    for (int off = 1; off < SCAN_B; off <<= 1) {
        int t = (tid >= off) ? sh[tid - off] : 0;
        __syncthreads();
        sh[tid] += t;
        __syncthreads();
    }
    int excl = red[0] + sh[tid] - v;  // exclusive prefix
    if (i < NN) { g_rowptr[i] = excl; g_cursor[i] = excl; }
    if (i == 0) g_rowptr[NN] = NE;
}

__global__ void k_fill(const int4* __restrict__ src4,
                       const int4* __restrict__ dst4) {
    int e = blockIdx.x * blockDim.x + threadIdx.x;
    if (e < NE / 4) {
        int4 s = src4[e];
        int4 d = dst4[e];
        g_col[atomicAdd(&g_cursor[d.x], 1)] = s.x;
        g_col[atomicAdd(&g_cursor[d.y], 1)] = s.y;
        g_col[atomicAdd(&g_cursor[d.z], 1)] = s.z;
        g_col[atomicAdd(&g_cursor[d.w], 1)] = s.w;
    }
}

// ---- gemm1 (lean, 1 row/thread, packed f32x2) — overlaps CSR build ----
__global__ void k_gemm1(const float* __restrict__ x,
                        const float* __restrict__ W1) {
    __shared__ float4 w4[DIN * HD / 4];  // 8KB; row k at w4[k*4..k*4+3]
    for (int t = threadIdx.x; t < DIN * HD / 4; t += blockDim.x)
        w4[t] = ((const float4*)W1)[t];
    __syncthreads();

    int row = blockIdx.x * blockDim.x + threadIdx.x;
    if (row >= NN) return;

    unsigned long long acc[8];
    #pragma unroll
    for (int i = 0; i < 8; i++) {
        unsigned long long z; PACK2(z, 0.0f); acc[i] = z;
    }

    const float4* xr = (const float4*)(x + (size_t)row * DIN);
    const unsigned long long* w2p = (const unsigned long long*)w4;
    #pragma unroll 4
    for (int kk = 0; kk < DIN / 4; kk++) {
        float4 xv = xr[kk];
        float xs[4] = {xv.x, xv.y, xv.z, xv.w};
        #pragma unroll
        for (int c = 0; c < 4; c++) {
            unsigned long long xb; PACK2(xb, xs[c]);
            const unsigned long long* wr = &w2p[(kk * 4 + c) * 8];
            #pragma unroll
            for (int i = 0; i < 8; i++) FMA2(acc[i], xb, wr[i]);
        }
    }

    float s = g_dis[row];
    float o[16];
    #pragma unroll
    for (int i = 0; i < 8; i++) {
        unsigned int lo, hi;
        asm("mov.b64 {%0, %1}, %2;" : "=r"(lo), "=r"(hi) : "l"(acc[i]));
        o[2 * i]     = __uint_as_float(lo) * s;
        o[2 * i + 1] = __uint_as_float(hi) * s;
    }
    float4* fp = &g_feat1[row * 4];
    fp[0] = make_float4(o[0],  o[1],  o[2],  o[3]);
    fp[1] = make_float4(o[4],  o[5],  o[6],  o[7]);
    fp[2] = make_float4(o[8],  o[9],  o[10], o[11]);
    fp[3] = make_float4(o[12], o[13], o[14], o[15]);
}

// ---- fused: agg1 (8 lanes/node, 4-way unrolled gather) + relu + gemm2 ----
// No early return: out-of-range lanes clamp to node NN-1 so all warps stay
// converged for the shuffles; stores are predicated.
__global__ void k_agg1g2(const float* __restrict__ b1,
                         const float* __restrict__ W2) {
    __shared__ float2 w2s[HD * HD / 2];  // [k*8+q] = W2[k][2q..2q+1]
    for (int t = threadIdx.x; t < HD * HD / 2; t += blockDim.x)
        w2s[t] = ((const float2*)W2)[t];
    __syncthreads();

    int t = blockIdx.x * blockDim.x + threadIdx.x;
    int node0 = t >> 3, q = t & 7;
    int node = node0 < NN ? node0 : NN - 1;

    const float2* f1 = (const float2*)g_feat1;
    float2 acc = f1[node * 8 + q];  // self-loop term
    int s = g_rowptr[node], e = g_rowptr[node + 1];
    int j = s;
    for (; j + 3 < e; j += 4) {   // batch 4 index loads, then 4 feature loads
        int c0 = g_col[j], c1 = g_col[j + 1], c2 = g_col[j + 2], c3 = g_col[j + 3];
        float2 v0 = f1[c0 * 8 + q];
        float2 v1 = f1[c1 * 8 + q];
        float2 v2 = f1[c2 * 8 + q];
        float2 v3 = f1[c3 * 8 + q];
        acc.x += v0.x + v1.x + v2.x + v3.x;
        acc.y += v0.y + v1.y + v2.y + v3.y;
    }
    for (; j < e; j++) {
        float2 v = f1[g_col[j] * 8 + q];
        acc.x += v.x; acc.y += v.y;
    }
    float ds = g_dis[node];
    float2 bb = ((const float2*)b1)[q];
    float h[2];
    h[0] = fmaxf(fmaf(acc.x, ds, bb.x), 0.f);
    h[1] = fmaxf(fmaf(acc.y, ds, bb.y), 0.f);

    // gemm2: o[2q..2q+1] = sum_k h_all[k] * W2[k][2q..2q+1]
    float2 o = {0.f, 0.f};
    #pragma unroll
    for (int k = 0; k < HD; k++) {
        float hk = __shfl_sync(0xffffffffu, h[k & 1], k >> 1, 8);
        float2 w = w2s[k * 8 + q];
        o.x = fmaf(hk, w.x, o.x);
        o.y = fmaf(hk, w.y, o.y);
    }
    o.x *= ds; o.y *= ds;
    if (node0 < NN) ((float2*)g_feat2)[node0 * 8 + q] = o;
}

// ---- agg2 (8 lanes/node, 4-way unrolled gather) + relu + fused head ----
__global__ void k_agg2h(const float* __restrict__ b2,
                        const float* __restrict__ Wl,
                        const float* __restrict__ bl,
                        float* __restrict__ out) {
    int t = blockIdx.x * blockDim.x + threadIdx.x;
    int node0 = t >> 3, q = t & 7;
    int node = node0 < NN ? node0 : NN - 1;

    const float2* f2 = (const float2*)g_feat2;
    float2 acc = f2[node * 8 + q];  // self-loop term
    int s = g_rowptr[node], e = g_rowptr[node + 1];
    int j = s;
    for (; j + 3 < e; j += 4) {
        int c0 = g_col[j], c1 = g_col[j + 1], c2 = g_col[j + 2], c3 = g_col[j + 3];
        float2 v0 = f2[c0 * 8 + q];
        float2 v1 = f2[c1 * 8 + q];
        float2 v2 = f2[c2 * 8 + q];
        float2 v3 = f2[c3 * 8 + q];
        acc.x += v0.x + v1.x + v2.x + v3.x;
        acc.y += v0.y + v1.y + v2.y + v3.y;
    }
    for (; j < e; j++) {
        float2 v = f2[g_col[j] * 8 + q];
        acc.x += v.x; acc.y += v.y;
    }
    float ds = g_dis[node];
    float2 bb = ((const float2*)b2)[q];
    float2 wl = ((const float2*)Wl)[q];
    float p = fmaxf(fmaf(acc.x, ds, bb.x), 0.f) * wl.x
            + fmaxf(fmaf(acc.y, ds, bb.y), 0.f) * wl.y;
    p += __shfl_xor_sync(0xffffffffu, p, 1, 8);
    p += __shfl_xor_sync(0xffffffffu, p, 2, 8);
    p += __shfl_xor_sync(0xffffffffu, p, 4, 8);
    if (q == 0 && node0 < NN) out[node0] = p + bl[0];
}

extern "C" void kernel_launch(void* const* d_in, const int* in_sizes, int n_in,
                              void* d_out, int out_size) {
    const float* x  = (const float*)d_in[0];
    const int*   ei = (const int*)d_in[1];    // int32 (JAX x64 disabled)
    const float* W1 = (const float*)d_in[2];
    const float* b1 = (const float*)d_in[3];
    const float* W2 = (const float*)d_in[4];
    const float* b2 = (const float*)d_in[5];
    const float* Wl = (const float*)d_in[6];
    const float* bl = (const float*)d_in[7];
    float* out = (float*)d_out;

    const int4* src4 = (const int4*)ei;          // edge_index[0]
    const int4* dst4 = (const int4*)(ei + NE);   // edge_index[1]

    // one-time stream/event setup (created on uncaptured correctness call, reused)
    static cudaStream_t s2 = nullptr;
    static cudaEvent_t evF = nullptr, evJ = nullptr;
    if (s2 == nullptr) {
        int leastPri = 0, greatestPri = 0;
        cudaDeviceGetStreamPriorityRange(&leastPri, &greatestPri);
        // gemm1 is the overlap "background" work: give it LOW priority so the
        // critical-path CSR kernels win SM slots during the overlap window.
        cudaStreamCreateWithPriority(&s2, cudaStreamNonBlocking, leastPri);
        cudaEventCreateWithFlags(&evF, cudaEventDisableTiming);
        cudaEventCreateWithFlags(&evJ, cudaEventDisableTiming);
    }

    k_zero        <<<(NN + 255) / 256, 256>>>();
    k_count       <<<(NE / 4 + 255) / 256, 256>>>(dst4);
    k_scan_partial<<<NSB, SCAN_B>>>();

    // fork: gemm1 depends only on g_dis (ready after scan_partial);
    // overlaps scan_final + fill on the main stream.
    cudaEventRecord(evF, 0);
    cudaStreamWaitEvent(s2, evF, 0);
    k_gemm1<<<(NN + 255) / 256, 256, 0, s2>>>(x, W1);
    cudaEventRecord(evJ, s2);

    k_scan_final  <<<NSB, SCAN_B>>>();
    k_fill        <<<(NE / 4 + 255) / 256, 256>>>(src4, dst4);

    // join: agg1g2 needs CSR (main) + feat1 (s2)
    cudaStreamWaitEvent(0, evJ, 0);
    k_agg1g2      <<<(NN * 8 + 255) / 256, 256>>>(b1, W2);
    k_agg2h       <<<(NN * 8 + 255) / 256, 256>>>(b2, Wl, bl, out);
}